// round 1
// baseline (speedup 1.0000x reference)
#include <cuda_runtime.h>
#include <math.h>

#define Bn 512
#define Tn 256
#define Cn 384
#define Hn 64

// Scratch for projected q/k/v: 3 x 32 MB static device arrays (allocation-free).
__device__ float g_q[(size_t)Bn * Tn * Hn];
__device__ float g_k[(size_t)Bn * Tn * Hn];
__device__ float g_v[(size_t)Bn * Tn * Hn];

// ---------------------------------------------------------------------------
// Projection kernel: computes k, q, v = x @ Wk|Wq|Wv
// M = B*T = 131072, K = 384, N = 3*64 = 192 fused.
// Tile: 64 rows x 192 cols per block, BK=32, 256 threads, 4x12 per thread.
// ---------------------------------------------------------------------------
__global__ __launch_bounds__(256) void proj_kernel(
    const float* __restrict__ x,
    const float* __restrict__ Wk,
    const float* __restrict__ Wq,
    const float* __restrict__ Wv)
{
    __shared__ float xs[32 * 68];    // [kk][row], row-pad 68 (float4-aligned)
    __shared__ float ws[32 * 192];   // [kk][col]: 0-63 Wk, 64-127 Wq, 128-191 Wv

    const int tid = threadIdx.x;
    const int ty  = tid >> 4;        // 0..15 -> rows ty*4 .. ty*4+3
    const int tx  = tid & 15;        // cols tx + 16*j
    const size_t row0 = (size_t)blockIdx.x * 64;

    float acc[4][12];
#pragma unroll
    for (int i = 0; i < 4; i++)
#pragma unroll
        for (int j = 0; j < 12; j++) acc[i][j] = 0.f;

    for (int kt = 0; kt < Cn; kt += 32) {
        // Stage x tile transposed: xs[c][r], gmem coalesced over c.
#pragma unroll
        for (int l = 0; l < 8; l++) {
            int idx = tid + l * 256;         // 0..2047
            int r = idx >> 5, c = idx & 31;
            xs[c * 68 + r] = x[(row0 + r) * Cn + kt + c];
        }
        // Stage the three weight tiles side by side.
#pragma unroll
        for (int l = 0; l < 8; l++) {
            int idx = tid + l * 256;         // 0..2047
            int kk = idx >> 6, n = idx & 63;
            int gw = (kt + kk) * Hn + n;
            ws[kk * 192 + n]       = Wk[gw];
            ws[kk * 192 + 64 + n]  = Wq[gw];
            ws[kk * 192 + 128 + n] = Wv[gw];
        }
        __syncthreads();

#pragma unroll
        for (int kk = 0; kk < 32; kk++) {
            float4 a4 = *reinterpret_cast<const float4*>(&xs[kk * 68 + ty * 4]);
            float a[4] = {a4.x, a4.y, a4.z, a4.w};
            float b[12];
#pragma unroll
            for (int j = 0; j < 12; j++) b[j] = ws[kk * 192 + tx + 16 * j];
#pragma unroll
            for (int i = 0; i < 4; i++)
#pragma unroll
                for (int j = 0; j < 12; j++)
                    acc[i][j] = fmaf(a[i], b[j], acc[i][j]);
        }
        __syncthreads();
    }

#pragma unroll
    for (int i = 0; i < 4; i++) {
        size_t r = row0 + ty * 4 + i;
#pragma unroll
        for (int j = 0; j < 12; j++) {
            int n = tx + 16 * j;
            float v = acc[i][j];
            if (n < 64)        g_k[r * Hn + n] = v;
            else if (n < 128)  g_q[r * Hn + (n - 64)] = v;
            else               g_v[r * Hn + (n - 128)] = v;
        }
    }
}

// ---------------------------------------------------------------------------
// Attention kernel: one block per (query tile of 64 rows, batch).
// Full score rows kept in smem (T=256 fits), exact softmax, then PV.
// Dynamic smem: S[64][260] + qst[64][68] + kv(max(kst,vs)) + linv[64]
// ---------------------------------------------------------------------------
#define S_LD   260
#define Q_LD   68
#define V_LD   68
#define SM_S   0
#define SM_Q   (64 * S_LD)               // 16640 floats
#define SM_KV  (SM_Q + 64 * Q_LD)        // +4352 -> 20992
#define SM_LNV (SM_KV + 256 * V_LD)      // +17408 -> 38400 (holds kst[64][260] too)
#define SM_FLOATS (SM_LNV + 64)          // 38464 floats = 153856 B

__global__ __launch_bounds__(256, 1) void attn_kernel(float* __restrict__ out)
{
    extern __shared__ float sm[];
    float* S    = sm + SM_S;     // scores / probs [64][S_LD]
    float* qst  = sm + SM_Q;     // q transposed   [h][t]
    float* kv   = sm + SM_KV;    // phase A: kst [h][s] (S_LD); phase C: vs [s][h] (V_LD)
    float* linv = sm + SM_LNV;   // 1/rowsum

    const int tid  = threadIdx.x;
    const int qt   = blockIdx.x;              // 0..3
    const int b    = blockIdx.y;              // 0..511
    const int kmax = (qt + 1) * 64;           // causal key span (multiple of 64)
    const float scale = rsqrtf((float)Cn);    // NOTE: C^-0.5, not H^-0.5
    const size_t base  = ((size_t)b * Tn) * Hn;
    const size_t qbase = base + (size_t)qt * 64 * Hn;

    // Stage q (pre-scaled, transposed) and k (transposed).
    for (int idx = tid; idx < 64 * Hn; idx += 256) {
        int t = idx >> 6, h = idx & 63;
        qst[h * Q_LD + t] = g_q[qbase + (size_t)t * Hn + h] * scale;
    }
    for (int idx = tid; idx < kmax * Hn; idx += 256) {
        int s = idx >> 6, h = idx & 63;
        kv[h * S_LD + s] = g_k[base + (size_t)s * Hn + h];
    }
    __syncthreads();

    // ---- Phase A: S[t][s] = q_t . k_s  (8x8 register tiles) ----
    {
        const int tgi = tid >> 5;   // 0..7  -> rows tgi*8..+7
        const int sgi = tid & 31;   // 0..31 -> cols sgi*8..+7
        if (sgi * 8 < kmax) {
            float acc[8][8];
#pragma unroll
            for (int i = 0; i < 8; i++)
#pragma unroll
                for (int j = 0; j < 8; j++) acc[i][j] = 0.f;

            for (int h = 0; h < Hn; h++) {
                float4 a0 = *reinterpret_cast<const float4*>(&qst[h * Q_LD + tgi * 8]);
                float4 a1 = *reinterpret_cast<const float4*>(&qst[h * Q_LD + tgi * 8 + 4]);
                float4 b0 = *reinterpret_cast<const float4*>(&kv[h * S_LD + sgi * 8]);
                float4 b1 = *reinterpret_cast<const float4*>(&kv[h * S_LD + sgi * 8 + 4]);
                float a[8] = {a0.x, a0.y, a0.z, a0.w, a1.x, a1.y, a1.z, a1.w};
                float bb[8] = {b0.x, b0.y, b0.z, b0.w, b1.x, b1.y, b1.z, b1.w};
#pragma unroll
                for (int i = 0; i < 8; i++)
#pragma unroll
                    for (int j = 0; j < 8; j++)
                        acc[i][j] = fmaf(a[i], bb[j], acc[i][j]);
            }
#pragma unroll
            for (int i = 0; i < 8; i++) {
                *reinterpret_cast<float4*>(&S[(tgi * 8 + i) * S_LD + sgi * 8]) =
                    make_float4(acc[i][0], acc[i][1], acc[i][2], acc[i][3]);
                *reinterpret_cast<float4*>(&S[(tgi * 8 + i) * S_LD + sgi * 8 + 4]) =
                    make_float4(acc[i][4], acc[i][5], acc[i][6], acc[i][7]);
            }
        }
    }
    __syncthreads();

    // ---- Phase B: causal mask + exact row softmax (4 threads/row), plus V staging ----
    {
        const int row = tid >> 2;          // 0..63
        const int q4  = tid & 3;           // quarter of the 256 columns
        const int c0  = q4 * 64;
        const int valid = qt * 64 + row + 1;           // causal: s <= t
        const int jend  = min(c0 + 64, valid);
        float* Srow = &S[row * S_LD];

        float lmax = -INFINITY;
        for (int j = c0; j < jend; j++) lmax = fmaxf(lmax, Srow[j]);
        lmax = fmaxf(lmax, __shfl_xor_sync(0xffffffffu, lmax, 1));
        lmax = fmaxf(lmax, __shfl_xor_sync(0xffffffffu, lmax, 2));

        float lsum = 0.f;
        for (int j = c0; j < jend; j++) {
            float p = __expf(Srow[j] - lmax);
            Srow[j] = p;
            lsum += p;
        }
        // Zero computed-but-masked entries so PV can loop 0..kmax unconditionally.
        int zs = jend > c0 ? jend : c0;
        int ze = min(c0 + 64, kmax);
        for (int j = zs; j < ze; j++) Srow[j] = 0.f;

        lsum += __shfl_xor_sync(0xffffffffu, lsum, 1);
        lsum += __shfl_xor_sync(0xffffffffu, lsum, 2);
        if (q4 == 0) linv[row] = 1.0f / lsum;
    }
    // Overwrite kst region with V[s][h] (kst reads finished at post-A barrier).
    for (int idx = tid; idx < kmax * Hn; idx += 256) {
        int s = idx >> 6, h = idx & 63;
        kv[s * V_LD + h] = g_v[base + (size_t)s * Hn + h];
    }
    __syncthreads();

    // ---- Phase C: out = (P @ V) * linv   (4x4 register tiles) ----
    {
        const int tr = tid >> 4;   // 0..15 -> rows tr*4..+3
        const int tc = tid & 15;   // cols tc*4..+3
        float accO[4][4];
#pragma unroll
        for (int i = 0; i < 4; i++)
#pragma unroll
            for (int j = 0; j < 4; j++) accO[i][j] = 0.f;

        for (int s = 0; s < kmax; s++) {
            float4 v = *reinterpret_cast<const float4*>(&kv[s * V_LD + tc * 4]);
#pragma unroll
            for (int i = 0; i < 4; i++) {
                float p = S[(tr * 4 + i) * S_LD + s];
                accO[i][0] = fmaf(p, v.x, accO[i][0]);
                accO[i][1] = fmaf(p, v.y, accO[i][1]);
                accO[i][2] = fmaf(p, v.z, accO[i][2]);
                accO[i][3] = fmaf(p, v.w, accO[i][3]);
            }
        }
#pragma unroll
        for (int i = 0; i < 4; i++) {
            int t = tr * 4 + i;
            float li = linv[t];
            float4 o = make_float4(accO[i][0] * li, accO[i][1] * li,
                                   accO[i][2] * li, accO[i][3] * li);
            *reinterpret_cast<float4*>(
                &out[((size_t)b * Tn + qt * 64 + t) * Hn + tc * 4]) = o;
        }
    }
}

extern "C" void kernel_launch(void* const* d_in, const int* in_sizes, int n_in,
                              void* d_out, int out_size)
{
    const float* x  = (const float*)d_in[0];
    const float* Wk = (const float*)d_in[1];
    const float* Wq = (const float*)d_in[2];
    const float* Wv = (const float*)d_in[3];
    float* out = (float*)d_out;

    cudaFuncSetAttribute(attn_kernel,
                         cudaFuncAttributeMaxDynamicSharedMemorySize,
                         SM_FLOATS * 4);

    proj_kernel<<<(Bn * Tn) / 64, 256>>>(x, Wk, Wq, Wv);
    attn_kernel<<<dim3(Tn / 64, Bn), 256, SM_FLOATS * 4>>>(out);
}

// round 5
// speedup vs baseline: 1.5768x; 1.5768x over previous
#include <cuda_runtime.h>
#include <math.h>
#include <stdint.h>

#define Bn 512
#define Tn 256
#define Cn 384
#define Hn 64

// Scratch for projected q/k/v (allocation-free).
__device__ float g_q[(size_t)Bn * Tn * Hn];
__device__ float g_k[(size_t)Bn * Tn * Hn];
__device__ float g_v[(size_t)Bn * Tn * Hn];

__device__ __forceinline__ uint32_t to_tf32(float f) {
    uint32_t u;
    asm("cvt.rna.tf32.f32 %0, %1;" : "=r"(u) : "f"(f));
    return u;
}

__device__ __forceinline__ void mma_tf32(float c[4], const uint32_t a[4],
                                         const uint32_t b[2]) {
    asm volatile(
        "mma.sync.aligned.m16n8k8.row.col.f32.tf32.tf32.f32 "
        "{%0,%1,%2,%3}, {%4,%5,%6,%7}, {%8,%9}, {%0,%1,%2,%3};\n"
        : "+f"(c[0]), "+f"(c[1]), "+f"(c[2]), "+f"(c[3])
        : "r"(a[0]), "r"(a[1]), "r"(a[2]), "r"(a[3]), "r"(b[0]), "r"(b[1]));
}

// ---------------------------------------------------------------------------
// Projection via mma.sync tf32 (baseline-PTX tensor path; no tcgen05 on this
// toolchain). CTA tile 128(M) x 192(N = Wk|Wq|Wv fused), K staged 32 wide.
// 8 warps, warp grid 2(M) x 4(N), warp tile 64 x 48 = 4x6 m16n8 tiles.
// smem: A [128][36] (bank-CF frag loads), B [32][200] (bank-CF frag loads).
// ---------------------------------------------------------------------------
#define A_LD 36
#define B_LD 200
#define SM_A 0
#define SM_B (128 * A_LD)               // 4608
#define SM_TOT (SM_B + 32 * B_LD)       // 11008 floats = 44032 B
#define ST_LD 68                        // epilogue staging [128][68] (8704 fl)

__global__ __launch_bounds__(256) void proj_mma_kernel(
    const float* __restrict__ x,
    const float* __restrict__ Wk,
    const float* __restrict__ Wq,
    const float* __restrict__ Wv)
{
    __shared__ __align__(16) float sm[SM_TOT];
    float* As = sm + SM_A;
    float* Bs = sm + SM_B;

    const int tid   = threadIdx.x;
    const int wid   = tid >> 5;
    const int lane  = tid & 31;
    const int gid   = lane >> 2;        // 0..7
    const int tig   = lane & 3;         // 0..3
    const int warpM = wid >> 2;         // 0..1 -> rows warpM*64
    const int warpN = wid & 3;          // 0..3 -> cols warpN*48
    const size_t row0 = (size_t)blockIdx.x * 128;

    float acc[4][6][4];
#pragma unroll
    for (int mi = 0; mi < 4; mi++)
#pragma unroll
        for (int ni = 0; ni < 6; ni++)
#pragma unroll
            for (int e = 0; e < 4; e++) acc[mi][ni][e] = 0.f;

    for (int kt = 0; kt < Cn / 32; kt++) {
        const int k0 = kt * 32;

        // Stage A [128 x 32] row-major, tf32-rounded. 4 float4 per thread.
#pragma unroll
        for (int j = 0; j < 4; j++) {
            int idx = tid + j * 256;
            int r = idx >> 3, c4 = idx & 7;
            float4 a = *reinterpret_cast<const float4*>(&x[(row0 + r) * Cn + k0 + c4 * 4]);
            uint4 u = make_uint4(to_tf32(a.x), to_tf32(a.y), to_tf32(a.z), to_tf32(a.w));
            *reinterpret_cast<uint4*>(&As[r * A_LD + c4 * 4]) = u;
        }
        // Stage B [32 x 192]: columns 0-63 Wk, 64-127 Wq, 128-191 Wv.
#pragma unroll
        for (int nt = 0; nt < 3; nt++) {
            const float* W = (nt == 0) ? Wk : (nt == 1) ? Wq : Wv;
#pragma unroll
            for (int j = 0; j < 2; j++) {
                int idx = tid + j * 256;
                int k = idx >> 4, n4 = idx & 15;
                float4 w = *reinterpret_cast<const float4*>(&W[(k0 + k) * Hn + n4 * 4]);
                uint4 u = make_uint4(to_tf32(w.x), to_tf32(w.y), to_tf32(w.z), to_tf32(w.w));
                *reinterpret_cast<uint4*>(&Bs[k * B_LD + nt * 64 + n4 * 4]) = u;
            }
        }
        __syncthreads();

#pragma unroll
        for (int ks = 0; ks < 4; ks++) {
            const int kk = ks * 8;
            uint32_t afr[4][4];
#pragma unroll
            for (int mi = 0; mi < 4; mi++) {
                int m = warpM * 64 + mi * 16;
                afr[mi][0] = __float_as_uint(As[(m + gid) * A_LD + kk + tig]);
                afr[mi][1] = __float_as_uint(As[(m + gid + 8) * A_LD + kk + tig]);
                afr[mi][2] = __float_as_uint(As[(m + gid) * A_LD + kk + tig + 4]);
                afr[mi][3] = __float_as_uint(As[(m + gid + 8) * A_LD + kk + tig + 4]);
            }
            uint32_t bfr[6][2];
#pragma unroll
            for (int ni = 0; ni < 6; ni++) {
                int n = warpN * 48 + ni * 8;
                bfr[ni][0] = __float_as_uint(Bs[(kk + tig) * B_LD + n + gid]);
                bfr[ni][1] = __float_as_uint(Bs[(kk + tig + 4) * B_LD + n + gid]);
            }
#pragma unroll
            for (int mi = 0; mi < 4; mi++)
#pragma unroll
                for (int ni = 0; ni < 6; ni++)
                    mma_tf32(acc[mi][ni], afr[mi], bfr[ni]);
        }
        __syncthreads();
    }

    // Epilogue: stage each 64-col output slab in smem, store coalesced.
    float* st = sm;  // reuse [128][68]
#pragma unroll
    for (int nt = 0; nt < 3; nt++) {
#pragma unroll
        for (int mi = 0; mi < 4; mi++)
#pragma unroll
            for (int ni = 0; ni < 6; ni++) {
                int nb = warpN * 48 + ni * 8;
                if ((nb >> 6) != nt) continue;
                int nloc = nb - nt * 64 + 2 * tig;
                int m = warpM * 64 + mi * 16 + gid;
                st[m * ST_LD + nloc]           = acc[mi][ni][0];
                st[m * ST_LD + nloc + 1]       = acc[mi][ni][1];
                st[(m + 8) * ST_LD + nloc]     = acc[mi][ni][2];
                st[(m + 8) * ST_LD + nloc + 1] = acc[mi][ni][3];
            }
        __syncthreads();
        float* dst = (nt == 0) ? g_k : (nt == 1) ? g_q : g_v;
#pragma unroll
        for (int j = 0; j < 8; j++) {
            int idx = tid + j * 256;
            int r = idx >> 4, c4 = idx & 15;
            float4 v = *reinterpret_cast<const float4*>(&st[r * ST_LD + c4 * 4]);
            *reinterpret_cast<float4*>(&dst[(row0 + r) * Hn + c4 * 4]) = v;
        }
        __syncthreads();
    }
}

// ---------------------------------------------------------------------------
// Attention kernel (unchanged — round-5 target).
// ---------------------------------------------------------------------------
#define S_LD   260
#define Q_LD   68
#define V_LD   68
#define SM_S   0
#define SM_Q   (64 * S_LD)
#define SM_KV  (SM_Q + 64 * Q_LD)
#define SM_LNV (SM_KV + 256 * V_LD)
#define SM_FLOATS (SM_LNV + 64)

__global__ __launch_bounds__(256, 1) void attn_kernel(float* __restrict__ out)
{
    extern __shared__ float sm[];
    float* S    = sm + SM_S;
    float* qst  = sm + SM_Q;
    float* kv   = sm + SM_KV;
    float* linv = sm + SM_LNV;

    const int tid  = threadIdx.x;
    const int qt   = blockIdx.x;
    const int b    = blockIdx.y;
    const int kmax = (qt + 1) * 64;
    const float scale = rsqrtf((float)Cn);
    const size_t base  = ((size_t)b * Tn) * Hn;
    const size_t qbase = base + (size_t)qt * 64 * Hn;

    for (int idx = tid; idx < 64 * Hn; idx += 256) {
        int t = idx >> 6, h = idx & 63;
        qst[h * Q_LD + t] = g_q[qbase + (size_t)t * Hn + h] * scale;
    }
    for (int idx = tid; idx < kmax * Hn; idx += 256) {
        int s = idx >> 6, h = idx & 63;
        kv[h * S_LD + s] = g_k[base + (size_t)s * Hn + h];
    }
    __syncthreads();

    {
        const int tgi = tid >> 5;
        const int sgi = tid & 31;
        if (sgi * 8 < kmax) {
            float acc[8][8];
#pragma unroll
            for (int i = 0; i < 8; i++)
#pragma unroll
                for (int j = 0; j < 8; j++) acc[i][j] = 0.f;

            for (int h = 0; h < Hn; h++) {
                float4 a0 = *reinterpret_cast<const float4*>(&qst[h * Q_LD + tgi * 8]);
                float4 a1 = *reinterpret_cast<const float4*>(&qst[h * Q_LD + tgi * 8 + 4]);
                float4 b0 = *reinterpret_cast<const float4*>(&kv[h * S_LD + sgi * 8]);
                float4 b1 = *reinterpret_cast<const float4*>(&kv[h * S_LD + sgi * 8 + 4]);
                float a[8] = {a0.x, a0.y, a0.z, a0.w, a1.x, a1.y, a1.z, a1.w};
                float bb[8] = {b0.x, b0.y, b0.z, b0.w, b1.x, b1.y, b1.z, b1.w};
#pragma unroll
                for (int i = 0; i < 8; i++)
#pragma unroll
                    for (int j = 0; j < 8; j++)
                        acc[i][j] = fmaf(a[i], bb[j], acc[i][j]);
            }
#pragma unroll
            for (int i = 0; i < 8; i++) {
                *reinterpret_cast<float4*>(&S[(tgi * 8 + i) * S_LD + sgi * 8]) =
                    make_float4(acc[i][0], acc[i][1], acc[i][2], acc[i][3]);
                *reinterpret_cast<float4*>(&S[(tgi * 8 + i) * S_LD + sgi * 8 + 4]) =
                    make_float4(acc[i][4], acc[i][5], acc[i][6], acc[i][7]);
            }
        }
    }
    __syncthreads();

    {
        const int row = tid >> 2;
        const int q4  = tid & 3;
        const int c0  = q4 * 64;
        const int valid = qt * 64 + row + 1;
        const int jend  = min(c0 + 64, valid);
        float* Srow = &S[row * S_LD];

        float lmax = -INFINITY;
        for (int j = c0; j < jend; j++) lmax = fmaxf(lmax, Srow[j]);
        lmax = fmaxf(lmax, __shfl_xor_sync(0xffffffffu, lmax, 1));
        lmax = fmaxf(lmax, __shfl_xor_sync(0xffffffffu, lmax, 2));

        float lsum = 0.f;
        for (int j = c0; j < jend; j++) {
            float p = __expf(Srow[j] - lmax);
            Srow[j] = p;
            lsum += p;
        }
        int zs = jend > c0 ? jend : c0;
        int ze = min(c0 + 64, kmax);
        for (int j = zs; j < ze; j++) Srow[j] = 0.f;

        lsum += __shfl_xor_sync(0xffffffffu, lsum, 1);
        lsum += __shfl_xor_sync(0xffffffffu, lsum, 2);
        if (q4 == 0) linv[row] = 1.0f / lsum;
    }
    for (int idx = tid; idx < kmax * Hn; idx += 256) {
        int s = idx >> 6, h = idx & 63;
        kv[s * V_LD + h] = g_v[base + (size_t)s * Hn + h];
    }
    __syncthreads();

    {
        const int tr = tid >> 4;
        const int tc = tid & 15;
        float accO[4][4];
#pragma unroll
        for (int i = 0; i < 4; i++)
#pragma unroll
            for (int j = 0; j < 4; j++) accO[i][j] = 0.f;

        for (int s = 0; s < kmax; s++) {
            float4 v = *reinterpret_cast<const float4*>(&kv[s * V_LD + tc * 4]);
#pragma unroll
            for (int i = 0; i < 4; i++) {
                float p = S[(tr * 4 + i) * S_LD + s];
                accO[i][0] = fmaf(p, v.x, accO[i][0]);
                accO[i][1] = fmaf(p, v.y, accO[i][1]);
                accO[i][2] = fmaf(p, v.z, accO[i][2]);
                accO[i][3] = fmaf(p, v.w, accO[i][3]);
            }
        }
#pragma unroll
        for (int i = 0; i < 4; i++) {
            int t = tr * 4 + i;
            float li = linv[t];
            float4 o = make_float4(accO[i][0] * li, accO[i][1] * li,
                                   accO[i][2] * li, accO[i][3] * li);
            *reinterpret_cast<float4*>(
                &out[((size_t)b * Tn + qt * 64 + t) * Hn + tc * 4]) = o;
        }
    }
}

extern "C" void kernel_launch(void* const* d_in, const int* in_sizes, int n_in,
                              void* d_out, int out_size)
{
    const float* x  = (const float*)d_in[0];
    const float* Wk = (const float*)d_in[1];
    const float* Wq = (const float*)d_in[2];
    const float* Wv = (const float*)d_in[3];
    float* out = (float*)d_out;

    cudaFuncSetAttribute(attn_kernel,
                         cudaFuncAttributeMaxDynamicSharedMemorySize,
                         SM_FLOATS * 4);

    proj_mma_kernel<<<(Bn * Tn) / 128, 256>>>(x, Wk, Wq, Wv);
    attn_kernel<<<dim3(Tn / 64, Bn), 256, SM_FLOATS * 4>>>(out);
}

// round 6
// speedup vs baseline: 3.1871x; 2.0212x over previous
#include <cuda_runtime.h>
#include <math.h>
#include <stdint.h>

#define Bn 512
#define Tn 256
#define Cn 384
#define Hn 64

// Scratch for projected q/k/v (allocation-free).
__device__ float g_q[(size_t)Bn * Tn * Hn];
__device__ float g_k[(size_t)Bn * Tn * Hn];
__device__ float g_v[(size_t)Bn * Tn * Hn];

__device__ __forceinline__ uint32_t to_tf32(float f) {
    uint32_t u;
    asm("cvt.rna.tf32.f32 %0, %1;" : "=r"(u) : "f"(f));
    return u;
}

__device__ __forceinline__ void mma_tf32(float c[4], const uint32_t a[4],
                                         const uint32_t b[2]) {
    asm volatile(
        "mma.sync.aligned.m16n8k8.row.col.f32.tf32.tf32.f32 "
        "{%0,%1,%2,%3}, {%4,%5,%6,%7}, {%8,%9}, {%0,%1,%2,%3};\n"
        : "+f"(c[0]), "+f"(c[1]), "+f"(c[2]), "+f"(c[3])
        : "r"(a[0]), "r"(a[1]), "r"(a[2]), "r"(a[3]), "r"(b[0]), "r"(b[1]));
}

// ---------------------------------------------------------------------------
// Projection via mma.sync tf32. CTA tile 128 x 192 (Wk|Wq|Wv fused), K=32
// staged. 8 warps, warp tile 64x48. (Unchanged from round 5: 199us.)
// ---------------------------------------------------------------------------
#define A_LD 36
#define B_LD 200
#define SM_A 0
#define SM_B (128 * A_LD)
#define SM_TOT (SM_B + 32 * B_LD)
#define ST_LD 68

__global__ __launch_bounds__(256) void proj_mma_kernel(
    const float* __restrict__ x,
    const float* __restrict__ Wk,
    const float* __restrict__ Wq,
    const float* __restrict__ Wv)
{
    __shared__ __align__(16) float sm[SM_TOT];
    float* As = sm + SM_A;
    float* Bs = sm + SM_B;

    const int tid   = threadIdx.x;
    const int wid   = tid >> 5;
    const int lane  = tid & 31;
    const int gid   = lane >> 2;
    const int tig   = lane & 3;
    const int warpM = wid >> 2;
    const int warpN = wid & 3;
    const size_t row0 = (size_t)blockIdx.x * 128;

    float acc[4][6][4];
#pragma unroll
    for (int mi = 0; mi < 4; mi++)
#pragma unroll
        for (int ni = 0; ni < 6; ni++)
#pragma unroll
            for (int e = 0; e < 4; e++) acc[mi][ni][e] = 0.f;

    for (int kt = 0; kt < Cn / 32; kt++) {
        const int k0 = kt * 32;
#pragma unroll
        for (int j = 0; j < 4; j++) {
            int idx = tid + j * 256;
            int r = idx >> 3, c4 = idx & 7;
            float4 a = *reinterpret_cast<const float4*>(&x[(row0 + r) * Cn + k0 + c4 * 4]);
            uint4 u = make_uint4(to_tf32(a.x), to_tf32(a.y), to_tf32(a.z), to_tf32(a.w));
            *reinterpret_cast<uint4*>(&As[r * A_LD + c4 * 4]) = u;
        }
#pragma unroll
        for (int nt = 0; nt < 3; nt++) {
            const float* W = (nt == 0) ? Wk : (nt == 1) ? Wq : Wv;
#pragma unroll
            for (int j = 0; j < 2; j++) {
                int idx = tid + j * 256;
                int k = idx >> 4, n4 = idx & 15;
                float4 w = *reinterpret_cast<const float4*>(&W[(k0 + k) * Hn + n4 * 4]);
                uint4 u = make_uint4(to_tf32(w.x), to_tf32(w.y), to_tf32(w.z), to_tf32(w.w));
                *reinterpret_cast<uint4*>(&Bs[k * B_LD + nt * 64 + n4 * 4]) = u;
            }
        }
        __syncthreads();

#pragma unroll
        for (int ks = 0; ks < 4; ks++) {
            const int kk = ks * 8;
            uint32_t afr[4][4];
#pragma unroll
            for (int mi = 0; mi < 4; mi++) {
                int m = warpM * 64 + mi * 16;
                afr[mi][0] = __float_as_uint(As[(m + gid) * A_LD + kk + tig]);
                afr[mi][1] = __float_as_uint(As[(m + gid + 8) * A_LD + kk + tig]);
                afr[mi][2] = __float_as_uint(As[(m + gid) * A_LD + kk + tig + 4]);
                afr[mi][3] = __float_as_uint(As[(m + gid + 8) * A_LD + kk + tig + 4]);
            }
            uint32_t bfr[6][2];
#pragma unroll
            for (int ni = 0; ni < 6; ni++) {
                int n = warpN * 48 + ni * 8;
                bfr[ni][0] = __float_as_uint(Bs[(kk + tig) * B_LD + n + gid]);
                bfr[ni][1] = __float_as_uint(Bs[(kk + tig + 4) * B_LD + n + gid]);
            }
#pragma unroll
            for (int mi = 0; mi < 4; mi++)
#pragma unroll
                for (int ni = 0; ni < 6; ni++)
                    mma_tf32(acc[mi][ni], afr[mi], bfr[ni]);
        }
        __syncthreads();
    }

    float* st = sm;
#pragma unroll
    for (int nt = 0; nt < 3; nt++) {
#pragma unroll
        for (int mi = 0; mi < 4; mi++)
#pragma unroll
            for (int ni = 0; ni < 6; ni++) {
                int nb = warpN * 48 + ni * 8;
                if ((nb >> 6) != nt) continue;
                int nloc = nb - nt * 64 + 2 * tig;
                int m = warpM * 64 + mi * 16 + gid;
                st[m * ST_LD + nloc]           = acc[mi][ni][0];
                st[m * ST_LD + nloc + 1]       = acc[mi][ni][1];
                st[(m + 8) * ST_LD + nloc]     = acc[mi][ni][2];
                st[(m + 8) * ST_LD + nloc + 1] = acc[mi][ni][3];
            }
        __syncthreads();
        float* dst = (nt == 0) ? g_k : (nt == 1) ? g_q : g_v;
#pragma unroll
        for (int j = 0; j < 8; j++) {
            int idx = tid + j * 256;
            int r = idx >> 4, c4 = idx & 15;
            float4 v = *reinterpret_cast<const float4*>(&st[r * ST_LD + c4 * 4]);
            *reinterpret_cast<float4*>(&dst[(row0 + r) * Hn + c4 * 4]) = v;
        }
        __syncthreads();
    }
}

// ---------------------------------------------------------------------------
// Attention v2: flash-style tf32 mma.sync. Block = (qt, b), 128 thr / 4 warps,
// warp owns 16 query rows. 64-key chunks, online softmax on C fragments.
// smem: qs[64][68] + ks[64][68] + vs[64][72] + ps[4][16][68] = 69KB -> 3 CTA/SM.
// ---------------------------------------------------------------------------
#define QS_LD 68
#define KS_LD 68
#define VS_LD 72
#define PS_LD 68
#define AT_QS 0
#define AT_KS (64 * QS_LD)                 // 4352
#define AT_VS (AT_KS + 64 * KS_LD)         // 8704
#define AT_PS (AT_VS + 64 * VS_LD)         // 13312
#define AT_FLOATS (AT_PS + 4 * 16 * PS_LD) // 17664 floats = 70656 B

__global__ __launch_bounds__(128, 3) void attn_mma_kernel(float* __restrict__ out)
{
    extern __shared__ float sm2[];
    float* qs  = sm2 + AT_QS;
    float* ks  = sm2 + AT_KS;
    float* vs  = sm2 + AT_VS;
    float* psw = sm2 + AT_PS + (threadIdx.x >> 5) * 16 * PS_LD;

    const int tid  = threadIdx.x;
    const int lane = tid & 31;
    const int gid  = lane >> 2;
    const int tig  = lane & 3;
    const int m0   = (tid >> 5) * 16;          // warp's 16-row tile
    const int qt   = blockIdx.x;
    const int b    = blockIdx.y;
    const float scale = rsqrtf((float)Cn);
    const size_t base = ((size_t)b * Tn) * Hn;

    // Stage q tile [64][64], scaled + tf32. Coalesced float4 reads.
    {
        const size_t qb = base + (size_t)qt * 64 * Hn;
#pragma unroll
        for (int it = 0; it < 8; it++) {
            int idx = tid + it * 128;
            int r = idx >> 4, h4 = idx & 15;
            float4 v = *reinterpret_cast<const float4*>(&g_q[qb + (size_t)r * Hn + h4 * 4]);
            uint4 u = make_uint4(to_tf32(v.x * scale), to_tf32(v.y * scale),
                                 to_tf32(v.z * scale), to_tf32(v.w * scale));
            *reinterpret_cast<uint4*>(&qs[r * QS_LD + h4 * 4]) = u;
        }
    }

    float o[8][4];
#pragma unroll
    for (int nt = 0; nt < 8; nt++)
#pragma unroll
        for (int e = 0; e < 4; e++) o[nt][e] = 0.f;
    float mrun0 = -INFINITY, mrun1 = -INFINITY;
    float lrun0 = 0.f, lrun1 = 0.f;

    for (int c = 0; c <= qt; c++) {
        __syncthreads();   // prev-chunk consumers done; also orders qs staging
        // Stage K chunk [s][h] (LD 68) and V chunk [s][h] (LD 72), tf32.
        const size_t kb = base + (size_t)c * 64 * Hn;
#pragma unroll
        for (int it = 0; it < 8; it++) {
            int idx = tid + it * 128;
            int r = idx >> 4, h4 = idx & 15;
            float4 kv4 = *reinterpret_cast<const float4*>(&g_k[kb + (size_t)r * Hn + h4 * 4]);
            uint4 ku = make_uint4(to_tf32(kv4.x), to_tf32(kv4.y), to_tf32(kv4.z), to_tf32(kv4.w));
            *reinterpret_cast<uint4*>(&ks[r * KS_LD + h4 * 4]) = ku;
            float4 vv4 = *reinterpret_cast<const float4*>(&g_v[kb + (size_t)r * Hn + h4 * 4]);
            uint4 vu = make_uint4(to_tf32(vv4.x), to_tf32(vv4.y), to_tf32(vv4.z), to_tf32(vv4.w));
            *reinterpret_cast<uint4*>(&vs[r * VS_LD + h4 * 4]) = vu;
        }
        __syncthreads();

        // S chunk = q . k^T : 8 ksteps x 8 ntiles of m16n8k8.
        float sacc[8][4];
#pragma unroll
        for (int nt = 0; nt < 8; nt++)
#pragma unroll
            for (int e = 0; e < 4; e++) sacc[nt][e] = 0.f;

#pragma unroll
        for (int kst = 0; kst < 8; kst++) {
            const int kk = kst * 8;
            uint32_t a[4];
            a[0] = __float_as_uint(qs[(m0 + gid) * QS_LD + kk + tig]);
            a[1] = __float_as_uint(qs[(m0 + gid + 8) * QS_LD + kk + tig]);
            a[2] = __float_as_uint(qs[(m0 + gid) * QS_LD + kk + tig + 4]);
            a[3] = __float_as_uint(qs[(m0 + gid + 8) * QS_LD + kk + tig + 4]);
#pragma unroll
            for (int nt = 0; nt < 8; nt++) {
                uint32_t bb[2];
                bb[0] = __float_as_uint(ks[(nt * 8 + gid) * KS_LD + kk + tig]);
                bb[1] = __float_as_uint(ks[(nt * 8 + gid) * KS_LD + kk + tig + 4]);
                mma_tf32(sacc[nt], a, bb);
            }
        }

        // Causal mask (diagonal chunk only) + online softmax update.
        const bool diag = (c == qt);
        const int rl0 = m0 + gid, rl1 = rl0 + 8;
        float cm0 = -INFINITY, cm1 = -INFINITY;
#pragma unroll
        for (int nt = 0; nt < 8; nt++)
#pragma unroll
            for (int e = 0; e < 2; e++) {
                int col = nt * 8 + 2 * tig + e;
                if (diag && col > rl0) sacc[nt][e]     = -INFINITY;
                if (diag && col > rl1) sacc[nt][2 + e] = -INFINITY;
                cm0 = fmaxf(cm0, sacc[nt][e]);
                cm1 = fmaxf(cm1, sacc[nt][2 + e]);
            }
        cm0 = fmaxf(cm0, __shfl_xor_sync(0xffffffffu, cm0, 1));
        cm0 = fmaxf(cm0, __shfl_xor_sync(0xffffffffu, cm0, 2));
        cm1 = fmaxf(cm1, __shfl_xor_sync(0xffffffffu, cm1, 1));
        cm1 = fmaxf(cm1, __shfl_xor_sync(0xffffffffu, cm1, 2));

        const float mn0 = fmaxf(mrun0, cm0);
        const float mn1 = fmaxf(mrun1, cm1);
        const float al0 = __expf(mrun0 - mn0);
        const float al1 = __expf(mrun1 - mn1);
        mrun0 = mn0; mrun1 = mn1;

        float sum0 = 0.f, sum1 = 0.f;
#pragma unroll
        for (int nt = 0; nt < 8; nt++)
#pragma unroll
            for (int e = 0; e < 2; e++) {
                float p0 = __expf(sacc[nt][e] - mn0);       // -inf -> 0
                float p1 = __expf(sacc[nt][2 + e] - mn1);
                sacc[nt][e] = p0; sacc[nt][2 + e] = p1;
                sum0 += p0; sum1 += p1;
            }
        sum0 += __shfl_xor_sync(0xffffffffu, sum0, 1);
        sum0 += __shfl_xor_sync(0xffffffffu, sum0, 2);
        sum1 += __shfl_xor_sync(0xffffffffu, sum1, 1);
        sum1 += __shfl_xor_sync(0xffffffffu, sum1, 2);
        lrun0 = lrun0 * al0 + sum0;
        lrun1 = lrun1 * al1 + sum1;

#pragma unroll
        for (int nt = 0; nt < 8; nt++) {
            o[nt][0] *= al0; o[nt][1] *= al0;
            o[nt][2] *= al1; o[nt][3] *= al1;
        }

        // P (tf32) -> warp-private smem in A layout.
#pragma unroll
        for (int nt = 0; nt < 8; nt++) {
            float2 p0 = make_float2(__uint_as_float(to_tf32(sacc[nt][0])),
                                    __uint_as_float(to_tf32(sacc[nt][1])));
            *reinterpret_cast<float2*>(&psw[gid * PS_LD + nt * 8 + 2 * tig]) = p0;
            float2 p1 = make_float2(__uint_as_float(to_tf32(sacc[nt][2])),
                                    __uint_as_float(to_tf32(sacc[nt][3])));
            *reinterpret_cast<float2*>(&psw[(gid + 8) * PS_LD + nt * 8 + 2 * tig]) = p1;
        }
        __syncwarp();

        // O += P @ V : 8 ksteps (s) x 8 ntiles (h).
#pragma unroll
        for (int kst = 0; kst < 8; kst++) {
            const int kk = kst * 8;
            uint32_t a[4];
            a[0] = __float_as_uint(psw[gid * PS_LD + kk + tig]);
            a[1] = __float_as_uint(psw[(gid + 8) * PS_LD + kk + tig]);
            a[2] = __float_as_uint(psw[gid * PS_LD + kk + tig + 4]);
            a[3] = __float_as_uint(psw[(gid + 8) * PS_LD + kk + tig + 4]);
#pragma unroll
            for (int nt = 0; nt < 8; nt++) {
                uint32_t bb[2];
                bb[0] = __float_as_uint(vs[(kk + tig) * VS_LD + nt * 8 + gid]);
                bb[1] = __float_as_uint(vs[(kk + tig + 4) * VS_LD + nt * 8 + gid]);
                mma_tf32(o[nt], a, bb);
            }
        }
    }

    // Epilogue: normalize and store.
    const float li0 = 1.0f / lrun0;
    const float li1 = 1.0f / lrun1;
    const size_t ob = ((size_t)b * Tn + qt * 64) * Hn;
#pragma unroll
    for (int nt = 0; nt < 8; nt++) {
        float2 v0 = make_float2(o[nt][0] * li0, o[nt][1] * li0);
        *reinterpret_cast<float2*>(&out[ob + (size_t)(m0 + gid) * Hn + nt * 8 + 2 * tig]) = v0;
        float2 v1 = make_float2(o[nt][2] * li1, o[nt][3] * li1);
        *reinterpret_cast<float2*>(&out[ob + (size_t)(m0 + gid + 8) * Hn + nt * 8 + 2 * tig]) = v1;
    }
}

extern "C" void kernel_launch(void* const* d_in, const int* in_sizes, int n_in,
                              void* d_out, int out_size)
{
    const float* x  = (const float*)d_in[0];
    const float* Wk = (const float*)d_in[1];
    const float* Wq = (const float*)d_in[2];
    const float* Wv = (const float*)d_in[3];
    float* out = (float*)d_out;

    cudaFuncSetAttribute(attn_mma_kernel,
                         cudaFuncAttributeMaxDynamicSharedMemorySize,
                         AT_FLOATS * 4);

    proj_mma_kernel<<<(Bn * Tn) / 128, 256>>>(x, Wk, Wq, Wv);
    attn_mma_kernel<<<dim3(Tn / 64, Bn), 128, AT_FLOATS * 4>>>(out);
}

// round 7
// speedup vs baseline: 3.8255x; 1.2003x over previous
#include <cuda_runtime.h>
#include <math.h>
#include <stdint.h>

#define Bn 512
#define Tn 256
#define Cn 384
#define Hn 64

// Scratch for projected q/k/v (allocation-free).
__device__ float g_q[(size_t)Bn * Tn * Hn];
__device__ float g_k[(size_t)Bn * Tn * Hn];
__device__ float g_v[(size_t)Bn * Tn * Hn];

__device__ __forceinline__ uint32_t smem_u32(const void* p) {
    uint32_t a;
    asm("{ .reg .u64 t; cvta.to.shared.u64 t, %1; cvt.u32.u64 %0, t; }"
        : "=r"(a) : "l"(p));
    return a;
}
__device__ __forceinline__ uint32_t to_tf32(float f) {
    uint32_t u;
    asm("cvt.rna.tf32.f32 %0, %1;" : "=r"(u) : "f"(f));
    return u;
}
__device__ __forceinline__ void mma_tf32(float c[4], const uint32_t a[4],
                                         const uint32_t b[2]) {
    asm volatile(
        "mma.sync.aligned.m16n8k8.row.col.f32.tf32.tf32.f32 "
        "{%0,%1,%2,%3}, {%4,%5,%6,%7}, {%8,%9}, {%0,%1,%2,%3};\n"
        : "+f"(c[0]), "+f"(c[1]), "+f"(c[2]), "+f"(c[3])
        : "r"(a[0]), "r"(a[1]), "r"(a[2]), "r"(a[3]), "r"(b[0]), "r"(b[1]));
}
#define CP_ASYNC16(dst, src) \
    asm volatile("cp.async.cg.shared.global [%0], [%1], 16;" :: "r"(dst), "l"(src))
#define CP_COMMIT() asm volatile("cp.async.commit_group;" ::: "memory")
#define CP_WAIT(N)  asm volatile("cp.async.wait_group %0;" :: "n"(N) : "memory")

// ---------------------------------------------------------------------------
// Projection v2: tf32 mma.sync + double-buffered cp.async pipeline.
// CTA tile 128 x 192 (Wk|Wq|Wv fused), BK=32, 8 warps, warp tile 64x48.
// Raw fp32 staged via cp.async; cvt.rna.tf32 applied at fragment-load time
// (numerically identical to staging-time cvt).
// ---------------------------------------------------------------------------
#define A_LD 36                          // 144 B/row (16B-aligned)
#define B_LD 200                         // 800 B/row (16B-aligned)
#define STAGE_FL (128 * A_LD + 32 * B_LD)   // 11008 floats per stage
#define P_SMEM_BYTES (2 * STAGE_FL * 4)     // 88064 B
#define ST_LD 68

__device__ __forceinline__ void proj_issue(
    const float* __restrict__ x, const float* __restrict__ Wk,
    const float* __restrict__ Wq, const float* __restrict__ Wv,
    float* As, float* Bs, int tid, size_t row0, int k0)
{
#pragma unroll
    for (int j = 0; j < 4; j++) {
        int idx = tid + j * 256;
        int r = idx >> 3, c4 = idx & 7;
        CP_ASYNC16(smem_u32(&As[r * A_LD + c4 * 4]),
                   &x[(row0 + r) * Cn + k0 + c4 * 4]);
    }
#pragma unroll
    for (int nt = 0; nt < 3; nt++) {
        const float* W = (nt == 0) ? Wk : (nt == 1) ? Wq : Wv;
#pragma unroll
        for (int j = 0; j < 2; j++) {
            int idx = tid + j * 256;
            int k = idx >> 4, n4 = idx & 15;
            CP_ASYNC16(smem_u32(&Bs[k * B_LD + nt * 64 + n4 * 4]),
                       &W[(k0 + k) * Hn + n4 * 4]);
        }
    }
}

__global__ __launch_bounds__(256) void proj_mma_kernel(
    const float* __restrict__ x,
    const float* __restrict__ Wk,
    const float* __restrict__ Wq,
    const float* __restrict__ Wv)
{
    extern __shared__ float smp[];

    const int tid   = threadIdx.x;
    const int wid   = tid >> 5;
    const int lane  = tid & 31;
    const int gid   = lane >> 2;
    const int tig   = lane & 3;
    const int warpM = wid >> 2;
    const int warpN = wid & 3;
    const size_t row0 = (size_t)blockIdx.x * 128;

    float acc[4][6][4];
#pragma unroll
    for (int mi = 0; mi < 4; mi++)
#pragma unroll
        for (int ni = 0; ni < 6; ni++)
#pragma unroll
            for (int e = 0; e < 4; e++) acc[mi][ni][e] = 0.f;

    // Prologue: prefetch k-iter 0 into stage 0.
    proj_issue(x, Wk, Wq, Wv, smp, smp + 128 * A_LD, tid, row0, 0);
    CP_COMMIT();

    for (int kt = 0; kt < Cn / 32; kt++) {
        const int buf = kt & 1;
        float* As = smp + buf * STAGE_FL;
        float* Bs = As + 128 * A_LD;

        if (kt + 1 < Cn / 32) {
            float* As2 = smp + (buf ^ 1) * STAGE_FL;
            proj_issue(x, Wk, Wq, Wv, As2, As2 + 128 * A_LD, tid, row0,
                       (kt + 1) * 32);
            CP_COMMIT();
            CP_WAIT(1);
        } else {
            CP_WAIT(0);
        }
        __syncthreads();

#pragma unroll
        for (int ks = 0; ks < 4; ks++) {
            const int kk = ks * 8;
            uint32_t afr[4][4];
#pragma unroll
            for (int mi = 0; mi < 4; mi++) {
                int m = warpM * 64 + mi * 16;
                afr[mi][0] = to_tf32(As[(m + gid) * A_LD + kk + tig]);
                afr[mi][1] = to_tf32(As[(m + gid + 8) * A_LD + kk + tig]);
                afr[mi][2] = to_tf32(As[(m + gid) * A_LD + kk + tig + 4]);
                afr[mi][3] = to_tf32(As[(m + gid + 8) * A_LD + kk + tig + 4]);
            }
            uint32_t bfr[6][2];
#pragma unroll
            for (int ni = 0; ni < 6; ni++) {
                int n = warpN * 48 + ni * 8;
                bfr[ni][0] = to_tf32(Bs[(kk + tig) * B_LD + n + gid]);
                bfr[ni][1] = to_tf32(Bs[(kk + tig + 4) * B_LD + n + gid]);
            }
#pragma unroll
            for (int mi = 0; mi < 4; mi++)
#pragma unroll
                for (int ni = 0; ni < 6; ni++)
                    mma_tf32(acc[mi][ni], afr[mi], bfr[ni]);
        }
        __syncthreads();   // all reads of this stage done before it is re-filled
    }

    // Epilogue: stage each 64-col output slab in smem, store coalesced.
    float* st = smp;  // reuse [128][68]
#pragma unroll
    for (int nt = 0; nt < 3; nt++) {
#pragma unroll
        for (int mi = 0; mi < 4; mi++)
#pragma unroll
            for (int ni = 0; ni < 6; ni++) {
                int nb = warpN * 48 + ni * 8;
                if ((nb >> 6) != nt) continue;
                int nloc = nb - nt * 64 + 2 * tig;
                int m = warpM * 64 + mi * 16 + gid;
                st[m * ST_LD + nloc]           = acc[mi][ni][0];
                st[m * ST_LD + nloc + 1]       = acc[mi][ni][1];
                st[(m + 8) * ST_LD + nloc]     = acc[mi][ni][2];
                st[(m + 8) * ST_LD + nloc + 1] = acc[mi][ni][3];
            }
        __syncthreads();
        float* dst = (nt == 0) ? g_k : (nt == 1) ? g_q : g_v;
#pragma unroll
        for (int j = 0; j < 8; j++) {
            int idx = tid + j * 256;
            int r = idx >> 4, c4 = idx & 15;
            float4 v = *reinterpret_cast<const float4*>(&st[r * ST_LD + c4 * 4]);
            *reinterpret_cast<float4*>(&dst[(row0 + r) * Hn + c4 * 4]) = v;
        }
        __syncthreads();
    }
}

// ---------------------------------------------------------------------------
// Attention: flash-style tf32 mma.sync (unchanged from round 6: 79.8us).
// ---------------------------------------------------------------------------
#define QS_LD 68
#define KS_LD 68
#define VS_LD 72
#define PS_LD 68
#define AT_QS 0
#define AT_KS (64 * QS_LD)
#define AT_VS (AT_KS + 64 * KS_LD)
#define AT_PS (AT_VS + 64 * VS_LD)
#define AT_FLOATS (AT_PS + 4 * 16 * PS_LD)

__global__ __launch_bounds__(128, 3) void attn_mma_kernel(float* __restrict__ out)
{
    extern __shared__ float sm2[];
    float* qs  = sm2 + AT_QS;
    float* ks  = sm2 + AT_KS;
    float* vs  = sm2 + AT_VS;
    float* psw = sm2 + AT_PS + (threadIdx.x >> 5) * 16 * PS_LD;

    const int tid  = threadIdx.x;
    const int lane = tid & 31;
    const int gid  = lane >> 2;
    const int tig  = lane & 3;
    const int m0   = (tid >> 5) * 16;
    const int qt   = blockIdx.x;
    const int b    = blockIdx.y;
    const float scale = rsqrtf((float)Cn);
    const size_t base = ((size_t)b * Tn) * Hn;

    {
        const size_t qb = base + (size_t)qt * 64 * Hn;
#pragma unroll
        for (int it = 0; it < 8; it++) {
            int idx = tid + it * 128;
            int r = idx >> 4, h4 = idx & 15;
            float4 v = *reinterpret_cast<const float4*>(&g_q[qb + (size_t)r * Hn + h4 * 4]);
            uint4 u = make_uint4(to_tf32(v.x * scale), to_tf32(v.y * scale),
                                 to_tf32(v.z * scale), to_tf32(v.w * scale));
            *reinterpret_cast<uint4*>(&qs[r * QS_LD + h4 * 4]) = u;
        }
    }

    float o[8][4];
#pragma unroll
    for (int nt = 0; nt < 8; nt++)
#pragma unroll
        for (int e = 0; e < 4; e++) o[nt][e] = 0.f;
    float mrun0 = -INFINITY, mrun1 = -INFINITY;
    float lrun0 = 0.f, lrun1 = 0.f;

    for (int c = 0; c <= qt; c++) {
        __syncthreads();
        const size_t kb = base + (size_t)c * 64 * Hn;
#pragma unroll
        for (int it = 0; it < 8; it++) {
            int idx = tid + it * 128;
            int r = idx >> 4, h4 = idx & 15;
            float4 kv4 = *reinterpret_cast<const float4*>(&g_k[kb + (size_t)r * Hn + h4 * 4]);
            uint4 ku = make_uint4(to_tf32(kv4.x), to_tf32(kv4.y), to_tf32(kv4.z), to_tf32(kv4.w));
            *reinterpret_cast<uint4*>(&ks[r * KS_LD + h4 * 4]) = ku;
            float4 vv4 = *reinterpret_cast<const float4*>(&g_v[kb + (size_t)r * Hn + h4 * 4]);
            uint4 vu = make_uint4(to_tf32(vv4.x), to_tf32(vv4.y), to_tf32(vv4.z), to_tf32(vv4.w));
            *reinterpret_cast<uint4*>(&vs[r * VS_LD + h4 * 4]) = vu;
        }
        __syncthreads();

        float sacc[8][4];
#pragma unroll
        for (int nt = 0; nt < 8; nt++)
#pragma unroll
            for (int e = 0; e < 4; e++) sacc[nt][e] = 0.f;

#pragma unroll
        for (int kst = 0; kst < 8; kst++) {
            const int kk = kst * 8;
            uint32_t a[4];
            a[0] = __float_as_uint(qs[(m0 + gid) * QS_LD + kk + tig]);
            a[1] = __float_as_uint(qs[(m0 + gid + 8) * QS_LD + kk + tig]);
            a[2] = __float_as_uint(qs[(m0 + gid) * QS_LD + kk + tig + 4]);
            a[3] = __float_as_uint(qs[(m0 + gid + 8) * QS_LD + kk + tig + 4]);
#pragma unroll
            for (int nt = 0; nt < 8; nt++) {
                uint32_t bb[2];
                bb[0] = __float_as_uint(ks[(nt * 8 + gid) * KS_LD + kk + tig]);
                bb[1] = __float_as_uint(ks[(nt * 8 + gid) * KS_LD + kk + tig + 4]);
                mma_tf32(sacc[nt], a, bb);
            }
        }

        const bool diag = (c == qt);
        const int rl0 = m0 + gid, rl1 = rl0 + 8;
        float cm0 = -INFINITY, cm1 = -INFINITY;
#pragma unroll
        for (int nt = 0; nt < 8; nt++)
#pragma unroll
            for (int e = 0; e < 2; e++) {
                int col = nt * 8 + 2 * tig + e;
                if (diag && col > rl0) sacc[nt][e]     = -INFINITY;
                if (diag && col > rl1) sacc[nt][2 + e] = -INFINITY;
                cm0 = fmaxf(cm0, sacc[nt][e]);
                cm1 = fmaxf(cm1, sacc[nt][2 + e]);
            }
        cm0 = fmaxf(cm0, __shfl_xor_sync(0xffffffffu, cm0, 1));
        cm0 = fmaxf(cm0, __shfl_xor_sync(0xffffffffu, cm0, 2));
        cm1 = fmaxf(cm1, __shfl_xor_sync(0xffffffffu, cm1, 1));
        cm1 = fmaxf(cm1, __shfl_xor_sync(0xffffffffu, cm1, 2));

        const float mn0 = fmaxf(mrun0, cm0);
        const float mn1 = fmaxf(mrun1, cm1);
        const float al0 = __expf(mrun0 - mn0);
        const float al1 = __expf(mrun1 - mn1);
        mrun0 = mn0; mrun1 = mn1;

        float sum0 = 0.f, sum1 = 0.f;
#pragma unroll
        for (int nt = 0; nt < 8; nt++)
#pragma unroll
            for (int e = 0; e < 2; e++) {
                float p0 = __expf(sacc[nt][e] - mn0);
                float p1 = __expf(sacc[nt][2 + e] - mn1);
                sacc[nt][e] = p0; sacc[nt][2 + e] = p1;
                sum0 += p0; sum1 += p1;
            }
        sum0 += __shfl_xor_sync(0xffffffffu, sum0, 1);
        sum0 += __shfl_xor_sync(0xffffffffu, sum0, 2);
        sum1 += __shfl_xor_sync(0xffffffffu, sum1, 1);
        sum1 += __shfl_xor_sync(0xffffffffu, sum1, 2);
        lrun0 = lrun0 * al0 + sum0;
        lrun1 = lrun1 * al1 + sum1;

#pragma unroll
        for (int nt = 0; nt < 8; nt++) {
            o[nt][0] *= al0; o[nt][1] *= al0;
            o[nt][2] *= al1; o[nt][3] *= al1;
        }

#pragma unroll
        for (int nt = 0; nt < 8; nt++) {
            float2 p0 = make_float2(__uint_as_float(to_tf32(sacc[nt][0])),
                                    __uint_as_float(to_tf32(sacc[nt][1])));
            *reinterpret_cast<float2*>(&psw[gid * PS_LD + nt * 8 + 2 * tig]) = p0;
            float2 p1 = make_float2(__uint_as_float(to_tf32(sacc[nt][2])),
                                    __uint_as_float(to_tf32(sacc[nt][3])));
            *reinterpret_cast<float2*>(&psw[(gid + 8) * PS_LD + nt * 8 + 2 * tig]) = p1;
        }
        __syncwarp();

#pragma unroll
        for (int kst = 0; kst < 8; kst++) {
            const int kk = kst * 8;
            uint32_t a[4];
            a[0] = __float_as_uint(psw[gid * PS_LD + kk + tig]);
            a[1] = __float_as_uint(psw[(gid + 8) * PS_LD + kk + tig]);
            a[2] = __float_as_uint(psw[gid * PS_LD + kk + tig + 4]);
            a[3] = __float_as_uint(psw[(gid + 8) * PS_LD + kk + tig + 4]);
#pragma unroll
            for (int nt = 0; nt < 8; nt++) {
                uint32_t bb[2];
                bb[0] = __float_as_uint(vs[(kk + tig) * VS_LD + nt * 8 + gid]);
                bb[1] = __float_as_uint(vs[(kk + tig + 4) * VS_LD + nt * 8 + gid]);
                mma_tf32(o[nt], a, bb);
            }
        }
    }

    const float li0 = 1.0f / lrun0;
    const float li1 = 1.0f / lrun1;
    const size_t ob = ((size_t)b * Tn + qt * 64) * Hn;
#pragma unroll
    for (int nt = 0; nt < 8; nt++) {
        float2 v0 = make_float2(o[nt][0] * li0, o[nt][1] * li0);
        *reinterpret_cast<float2*>(&out[ob + (size_t)(m0 + gid) * Hn + nt * 8 + 2 * tig]) = v0;
        float2 v1 = make_float2(o[nt][2] * li1, o[nt][3] * li1);
        *reinterpret_cast<float2*>(&out[ob + (size_t)(m0 + gid + 8) * Hn + nt * 8 + 2 * tig]) = v1;
    }
}

extern "C" void kernel_launch(void* const* d_in, const int* in_sizes, int n_in,
                              void* d_out, int out_size)
{
    const float* x  = (const float*)d_in[0];
    const float* Wk = (const float*)d_in[1];
    const float* Wq = (const float*)d_in[2];
    const float* Wv = (const float*)d_in[3];
    float* out = (float*)d_out;

    cudaFuncSetAttribute(proj_mma_kernel,
                         cudaFuncAttributeMaxDynamicSharedMemorySize, P_SMEM_BYTES);
    cudaFuncSetAttribute(attn_mma_kernel,
                         cudaFuncAttributeMaxDynamicSharedMemorySize, AT_FLOATS * 4);

    proj_mma_kernel<<<(Bn * Tn) / 128, 256, P_SMEM_BYTES>>>(x, Wk, Wq, Wv);
    attn_mma_kernel<<<dim3(Tn / 64, Bn), 128, AT_FLOATS * 4>>>(out);
}